// round 3
// baseline (speedup 1.0000x reference)
#include <cuda_runtime.h>
#include <cstdint>

// SINDy_SHRED: 10 Euler steps of z += Theta(z) @ (C*mask) * dt
// per (sample, replicate). Theta = [1, z, z_i z_j (i<=j), sin(z)] -> 169 rows.
//
// R3: identical math to R2 but every SMEM coefficient read goes through
// asm volatile ld.shared.v4.f32. Rounds 1-2 both spilled exactly 1792 B/thread
// (tripping the allocation guard) because ptxas hoisted the loop-invariant
// coefficient table (2704 floats) across the 10-step loop and spilled the
// overflow. asm volatile is un-hoistable -> bounded register pressure.

#define LATENT 16
#define NFEAT 169
#define NSTEPS 10
#define DT_F 0.01f

__host__ __device__ __forceinline__ constexpr int quad_row(int i, int j) {
    return 17 + 16 * i - (i * (i - 1)) / 2 + (j - i);
}

__device__ __forceinline__ void lds4(uint32_t addr, float& a, float& b, float& c, float& d) {
    asm volatile("ld.shared.v4.f32 {%0, %1, %2, %3}, [%4];"
                 : "=f"(a), "=f"(b), "=f"(c), "=f"(d) : "r"(addr));
}

__global__ __launch_bounds__(256) void sindy_shred_kernel(
    const float* __restrict__ h_t,
    const float* __restrict__ coef,
    const float* __restrict__ mask,
    float* __restrict__ out,
    int n, int nrep)
{
    // Masked coefficients for this block's replicate: row-major [169][16].
    __shared__ float sC[NFEAT * LATENT];

    const int r = blockIdx.y;
    const float* cbase = coef + (size_t)r * NFEAT * LATENT;
    const float* mbase = mask + (size_t)r * NFEAT * LATENT;
    for (int idx = threadIdx.x; idx < NFEAT * LATENT; idx += blockDim.x)
        sC[idx] = cbase[idx] * mbase[idx];
    __syncthreads();

    const uint32_t sbase = (uint32_t)__cvta_generic_to_shared(sC);

    const int sample = blockIdx.x * blockDim.x + threadIdx.x;
    if (sample >= n) return;

    float z[LATENT];
    {
        const float* hp = h_t + (size_t)sample * LATENT;
        #pragma unroll
        for (int d = 0; d < LATENT; d++) z[d] = hp[d];
    }

    #pragma unroll 1
    for (int s = 0; s < NSTEPS; s++) {
        float acc[LATENT];

        // row 0: constant feature (theta = 1) -> acc = C[0][:]
        #pragma unroll
        for (int q = 0; q < 4; q++)
            lds4(sbase + q * 16u,
                 acc[4 * q + 0], acc[4 * q + 1], acc[4 * q + 2], acc[4 * q + 3]);

        // rows 1..16: linear, theta = z_i
        #pragma unroll
        for (int i = 0; i < LATENT; i++) {
            const float t = z[i];
            const uint32_t base = sbase + (uint32_t)(1 + i) * 64u;
            #pragma unroll
            for (int q = 0; q < 4; q++) {
                float c0, c1, c2, c3;
                lds4(base + q * 16u, c0, c1, c2, c3);
                acc[4 * q + 0] = fmaf(t, c0, acc[4 * q + 0]);
                acc[4 * q + 1] = fmaf(t, c1, acc[4 * q + 1]);
                acc[4 * q + 2] = fmaf(t, c2, acc[4 * q + 2]);
                acc[4 * q + 3] = fmaf(t, c3, acc[4 * q + 3]);
            }
        }

        // rows 17..152: quadratic, theta = z_i * z_j (i<=j)
        #pragma unroll
        for (int i = 0; i < LATENT; i++) {
            #pragma unroll
            for (int j = i; j < LATENT; j++) {
                const float t = z[i] * z[j];
                const uint32_t base = sbase + (uint32_t)quad_row(i, j) * 64u;
                #pragma unroll
                for (int q = 0; q < 4; q++) {
                    float c0, c1, c2, c3;
                    lds4(base + q * 16u, c0, c1, c2, c3);
                    acc[4 * q + 0] = fmaf(t, c0, acc[4 * q + 0]);
                    acc[4 * q + 1] = fmaf(t, c1, acc[4 * q + 1]);
                    acc[4 * q + 2] = fmaf(t, c2, acc[4 * q + 2]);
                    acc[4 * q + 3] = fmaf(t, c3, acc[4 * q + 3]);
                }
            }
        }

        // rows 153..168: sine, theta = sin(z_i)
        #pragma unroll
        for (int i = 0; i < LATENT; i++) {
            const float t = __sinf(z[i]);
            const uint32_t base = sbase + (uint32_t)(153 + i) * 64u;
            #pragma unroll
            for (int q = 0; q < 4; q++) {
                float c0, c1, c2, c3;
                lds4(base + q * 16u, c0, c1, c2, c3);
                acc[4 * q + 0] = fmaf(t, c0, acc[4 * q + 0]);
                acc[4 * q + 1] = fmaf(t, c1, acc[4 * q + 1]);
                acc[4 * q + 2] = fmaf(t, c2, acc[4 * q + 2]);
                acc[4 * q + 3] = fmaf(t, c3, acc[4 * q + 3]);
            }
        }

        // Euler update: z += dz * dt
        #pragma unroll
        for (int d = 0; d < LATENT; d++)
            z[d] = fmaf(acc[d], DT_F, z[d]);
    }

    // out layout: [n, nrep, 16]
    float* op = out + ((size_t)sample * nrep + r) * LATENT;
    #pragma unroll
    for (int d = 0; d < LATENT; d++) op[d] = z[d];
}

extern "C" void kernel_launch(void* const* d_in, const int* in_sizes, int n_in,
                              void* d_out, int out_size) {
    const float* h_t  = (const float*)d_in[0];
    const float* coef = (const float*)d_in[1];
    const float* mask = (const float*)d_in[2];
    float* out = (float*)d_out;

    int n    = in_sizes[0] / LATENT;            // samples
    int nrep = in_sizes[1] / (NFEAT * LATENT);  // replicates

    dim3 block(256);
    dim3 grid((n + 255) / 256, nrep);
    sindy_shred_kernel<<<grid, block>>>(h_t, coef, mask, out, n, nrep);
}